// round 1
// baseline (speedup 1.0000x reference)
#include <cuda_runtime.h>
#include <cstdint>

// Problem constants
#define NB    4
#define LSEQ  2048
#define DIN   1024
#define DQK   512
#define DV    512
#define X_ELEMS   (NB * LSEQ * DIN)   // 8388608
#define CTX_ELEMS (NB * LSEQ * DV)    // 4194304

// Scratch (allocation-free rule: __device__ globals)
__device__ float g_qp[NB * LSEQ * DQK];
__device__ float g_kp[NB * LSEQ * DQK];
__device__ float g_vp[NB * LSEQ * DV];
__device__ float g_sc[(size_t)NB * LSEQ * LSEQ];
__device__ int   g_maskmode;   // 0 = u8, 1 = i32, 2 = f32

// ---------------------------------------------------------------------------
// Mask dtype sniffer: inspect first 4096 bytes of the mask buffer.
//   u8  layout: nonzero bytes appear at offset%4==1 (random 0/1 bytes)
//   f32 layout (0.0f/1.0f): nonzero only at %4==2 (0x80) and %4==3 (0x3F)
//   i32 layout: nonzero only at %4==0
// ---------------------------------------------------------------------------
__global__ void detect_mask_kernel(const unsigned char* __restrict__ m) {
    __shared__ int f1, f3;
    if (threadIdx.x == 0) { f1 = 0; f3 = 0; }
    __syncthreads();
    int nz1 = 0, nz3 = 0;
    for (int i = threadIdx.x; i < 4096; i += blockDim.x) {
        unsigned char c = m[i];
        if (c) {
            int r = i & 3;
            if (r == 1) nz1 = 1;
            if (r == 3) nz3 = 1;
        }
    }
    if (nz1) atomicOr(&f1, 1);
    if (nz3) atomicOr(&f3, 1);
    __syncthreads();
    if (threadIdx.x == 0)
        g_maskmode = f1 ? 0 : (f3 ? 2 : 1);
}

__device__ __forceinline__ bool mask_at(const unsigned char* __restrict__ m, long long idx) {
    int mode = g_maskmode;
    if (mode == 0) return m[idx] != 0;
    if (mode == 1) return ((const int*)m)[idx] != 0;
    return ((const float*)m)[idx] != 0.0f;
}

// ---------------------------------------------------------------------------
// Tiled fp32 GEMM: C[M,N] = alpha * A[M,K] @ op(B)
//   BKN == 0: B is [N,K] row-major (NT; for x @ W^T and qp @ kp^T)
//   BKN == 1: B is [K,N] row-major (NN; for attn @ vp)
//   EPI == 0: plain store
//   EPI == 1: scores epilogue: masked -> -inf, else * alpha
// Tile 128x128, BK=8, 256 threads, 8x8 per-thread register tile.
// Requires M%128==0, N%128==0, K%8==0 (all true for this problem).
// ---------------------------------------------------------------------------
template <int BKN, int EPI>
__global__ __launch_bounds__(256, 2)
void gemm128x128(const float* __restrict__ A, const float* __restrict__ B,
                 float* __restrict__ C, int M, int N, int K,
                 long long sA, long long sB, long long sC,
                 float alpha, const unsigned char* __restrict__ mask)
{
    const int bz = blockIdx.z;
    A += (long long)bz * sA;
    B += (long long)bz * sB;
    C += (long long)bz * sC;

    __shared__ __align__(16) float As[8][132];
    __shared__ __align__(16) float Bs[8][132];

    const int tid   = threadIdx.x;
    const int tx    = tid & 15;          // 0..15 -> N direction
    const int ty    = tid >> 4;          // 0..15 -> M direction
    const int tileM = blockIdx.y * 128;
    const int tileN = blockIdx.x * 128;

    // A tile load mapping: 128 rows x 8 k, float4 along K
    const int aRow = tid >> 1;           // 0..127
    const int aCol = (tid & 1) << 2;     // 0 or 4
    const float* Ap = A + (long long)(tileM + aRow) * K + aCol;

    const float* Bp;
    int bRow = 0, bCol = 0;
    if (BKN) {                           // B[K,N]: 8 k-rows x 128 n, float4 along N
        bRow = tid >> 5;                 // 0..7
        bCol = (tid & 31) << 2;          // 0..124
        Bp = B + (long long)bRow * N + tileN + bCol;
    } else {                             // B[N,K]: same mapping as A
        Bp = B + (long long)(tileN + aRow) * K + aCol;
    }

    float acc[8][8];
#pragma unroll
    for (int i = 0; i < 8; i++)
#pragma unroll
        for (int j = 0; j < 8; j++) acc[i][j] = 0.f;

    for (int k0 = 0; k0 < K; k0 += 8) {
        float4 av = *(const float4*)(Ap + k0);
        As[aCol + 0][aRow] = av.x;
        As[aCol + 1][aRow] = av.y;
        As[aCol + 2][aRow] = av.z;
        As[aCol + 3][aRow] = av.w;
        if (BKN) {
            float4 bv = *(const float4*)(Bp + (long long)k0 * N);
            *(float4*)&Bs[bRow][bCol] = bv;
        } else {
            float4 bv = *(const float4*)(Bp + k0);
            Bs[aCol + 0][aRow] = bv.x;
            Bs[aCol + 1][aRow] = bv.y;
            Bs[aCol + 2][aRow] = bv.z;
            Bs[aCol + 3][aRow] = bv.w;
        }
        __syncthreads();
#pragma unroll
        for (int kk = 0; kk < 8; kk++) {
            float4 a0 = *(const float4*)&As[kk][ty * 8];
            float4 a1 = *(const float4*)&As[kk][ty * 8 + 4];
            float4 b0 = *(const float4*)&Bs[kk][tx * 8];
            float4 b1 = *(const float4*)&Bs[kk][tx * 8 + 4];
            float ar[8] = {a0.x, a0.y, a0.z, a0.w, a1.x, a1.y, a1.z, a1.w};
            float br[8] = {b0.x, b0.y, b0.z, b0.w, b1.x, b1.y, b1.z, b1.w};
#pragma unroll
            for (int i = 0; i < 8; i++)
#pragma unroll
                for (int j = 0; j < 8; j++)
                    acc[i][j] = fmaf(ar[i], br[j], acc[i][j]);
        }
        __syncthreads();
    }

    const float NEG_INF = __int_as_float(0xff800000);
#pragma unroll
    for (int i = 0; i < 8; i++) {
        int row = tileM + ty * 8 + i;
        long long cbase = (long long)row * N + tileN + tx * 8;
        float out[8];
        if (EPI == 1) {
            long long mbase = (long long)bz * ((long long)M * N) + cbase;
#pragma unroll
            for (int j = 0; j < 8; j++) {
                bool mk = mask_at(mask, mbase + j);
                out[j] = mk ? NEG_INF : acc[i][j] * alpha;
            }
        } else {
#pragma unroll
            for (int j = 0; j < 8; j++) out[j] = acc[i][j];
        }
        *(float4*)&C[cbase]     = make_float4(out[0], out[1], out[2], out[3]);
        *(float4*)&C[cbase + 4] = make_float4(out[4], out[5], out[6], out[7]);
    }
}

// ---------------------------------------------------------------------------
// Row softmax over LSEQ=2048 columns. One block (256 threads) per row.
// Masked entries already hold -inf -> exp() == 0.
// ---------------------------------------------------------------------------
__global__ void softmax_rows(float* __restrict__ S) {
    float* row = S + (long long)blockIdx.x * LSEQ;
    const int tid = threadIdx.x;   // 256 threads, 8 elems each

    float v[8];
    float mx = -3.4e38f;
#pragma unroll
    for (int i = 0; i < 8; i++) {
        v[i] = row[tid + (i << 8)];
        mx = fmaxf(mx, v[i]);
    }
    __shared__ float red[8];
#pragma unroll
    for (int o = 16; o > 0; o >>= 1)
        mx = fmaxf(mx, __shfl_xor_sync(0xffffffffu, mx, o));
    if ((tid & 31) == 0) red[tid >> 5] = mx;
    __syncthreads();
    mx = red[0];
#pragma unroll
    for (int w = 1; w < 8; w++) mx = fmaxf(mx, red[w]);
    __syncthreads();

    float s = 0.f;
#pragma unroll
    for (int i = 0; i < 8; i++) {
        v[i] = __expf(v[i] - mx);
        s += v[i];
    }
#pragma unroll
    for (int o = 16; o > 0; o >>= 1)
        s += __shfl_xor_sync(0xffffffffu, s, o);
    if ((tid & 31) == 0) red[tid >> 5] = s;
    __syncthreads();
    s = 0.f;
#pragma unroll
    for (int w = 0; w < 8; w++) s += red[w];

    float inv = 1.0f / s;
#pragma unroll
    for (int i = 0; i < 8; i++)
        row[tid + (i << 8)] = v[i] * inv;
}

// ---------------------------------------------------------------------------
// Launch
// Inputs: 0=q 1=k 2=v 3=softmax_mask 4=Wq 5=Wk 6=Wv 7=Wfc
// Output: concat(x [B,L,1024], ctx [B,L,512]) as float
// ---------------------------------------------------------------------------
extern "C" void kernel_launch(void* const* d_in, const int* in_sizes, int n_in,
                              void* d_out, int out_size)
{
    const float* q    = (const float*)d_in[0];
    const float* k    = (const float*)d_in[1];
    const float* v    = (const float*)d_in[2];
    const unsigned char* mask = (const unsigned char*)d_in[3];
    const float* Wq   = (const float*)d_in[4];
    const float* Wk   = (const float*)d_in[5];
    const float* Wv   = (const float*)d_in[6];
    const float* Wfc  = (const float*)d_in[7];

    float* out = (float*)d_out;
    float* xo  = out;             // (B,L,1024)
    float* ctx = out + X_ELEMS;   // (B,L,512)

    float *qp, *kp, *vp, *sc;
    cudaGetSymbolAddress((void**)&qp, g_qp);
    cudaGetSymbolAddress((void**)&kp, g_kp);
    cudaGetSymbolAddress((void**)&vp, g_vp);
    cudaGetSymbolAddress((void**)&sc, g_sc);

    detect_mask_kernel<<<1, 256>>>(mask);

    dim3 blk(256);

    // Projections: (B*L, DIN) @ W^T -> (B*L, 512). M=8192, N=512, K=1024.
    dim3 gp(DQK / 128, (NB * LSEQ) / 128, 1);
    gemm128x128<0, 0><<<gp, blk>>>(q, Wq, qp, NB * LSEQ, DQK, DIN, 0, 0, 0, 1.f, nullptr);
    gemm128x128<0, 0><<<gp, blk>>>(k, Wk, kp, NB * LSEQ, DQK, DIN, 0, 0, 0, 1.f, nullptr);
    gemm128x128<0, 0><<<gp, blk>>>(v, Wv, vp, NB * LSEQ, DV,  DIN, 0, 0, 0, 1.f, nullptr);

    // Scores: per batch qp @ kp^T / 8, mask -> -inf. M=N=2048, K=512.
    dim3 gs(LSEQ / 128, LSEQ / 128, NB);
    gemm128x128<0, 1><<<gs, blk>>>(qp, kp, sc, LSEQ, LSEQ, DQK,
                                   (long long)LSEQ * DQK, (long long)LSEQ * DQK,
                                   (long long)LSEQ * LSEQ,
                                   0.125f /* 1/sqrt(64) */, mask);

    // Softmax over key dim.
    softmax_rows<<<NB * LSEQ, 256>>>(sc);

    // ctx = attn @ vp. M=2048, N=512, K=2048 per batch. B is [K,N].
    dim3 gc(DV / 128, LSEQ / 128, NB);
    gemm128x128<1, 0><<<gc, blk>>>(sc, vp, ctx, LSEQ, DV, LSEQ,
                                   (long long)LSEQ * LSEQ, (long long)LSEQ * DV,
                                   (long long)LSEQ * DV, 1.f, nullptr);

    // x = ctx @ Wfc^T. Batches merge: M=8192, N=1024, K=512.
    dim3 gx(DIN / 128, (NB * LSEQ) / 128, 1);
    gemm128x128<0, 0><<<gx, blk>>>(ctx, Wfc, xo, NB * LSEQ, DIN, DV, 0, 0, 0, 1.f, nullptr);
}

// round 3
// speedup vs baseline: 1.0010x; 1.0010x over previous
#include <cuda_runtime.h>
#include <cstdint>

// Problem constants
#define NB    4
#define LSEQ  2048
#define DIN   1024
#define DQK   512
#define DV    512
#define X_ELEMS   (NB * LSEQ * DIN)   // 8388608
#define CTX_ELEMS (NB * LSEQ * DV)    // 4194304

// Scratch (allocation-free rule: __device__ globals)
__device__ float g_qp[NB * LSEQ * DQK];
__device__ float g_kp[NB * LSEQ * DQK];
__device__ float g_vp[NB * LSEQ * DV];
__device__ float g_sc[(size_t)NB * LSEQ * LSEQ];
__device__ int   g_maskmode;   // 0 = u8, 1 = i32, 2 = f32

// ---------------------------------------------------------------------------
// Mask dtype sniffer: inspect first 4096 bytes of the mask buffer.
//   u8  layout: nonzero bytes appear at offset%4==1 (random 0/1 bytes)
//   f32 layout (0.0f/1.0f): nonzero only at %4==2 (0x80) and %4==3 (0x3F)
//   i32 layout: nonzero only at %4==0
// ---------------------------------------------------------------------------
__global__ void detect_mask_kernel(const unsigned char* __restrict__ m) {
    __shared__ int f1, f3;
    if (threadIdx.x == 0) { f1 = 0; f3 = 0; }
    __syncthreads();
    int nz1 = 0, nz3 = 0;
    for (int i = threadIdx.x; i < 4096; i += blockDim.x) {
        unsigned char c = m[i];
        if (c) {
            int r = i & 3;
            if (r == 1) nz1 = 1;
            if (r == 3) nz3 = 1;
        }
    }
    if (nz1) atomicOr(&f1, 1);
    if (nz3) atomicOr(&f3, 1);
    __syncthreads();
    if (threadIdx.x == 0)
        g_maskmode = f1 ? 0 : (f3 ? 2 : 1);
}

__device__ __forceinline__ bool mask_at(const unsigned char* __restrict__ m, long long idx) {
    int mode = g_maskmode;
    if (mode == 0) return m[idx] != 0;
    if (mode == 1) return ((const int*)m)[idx] != 0;
    return ((const float*)m)[idx] != 0.0f;
}

// ---------------------------------------------------------------------------
// Tiled fp32 GEMM: C[M,N] = alpha * A[M,K] @ op(B)
//   BKN == 0: B is [N,K] row-major (NT; for x @ W^T and qp @ kp^T)
//   BKN == 1: B is [K,N] row-major (NN; for attn @ vp)
//   EPI == 0: plain store
//   EPI == 1: scores epilogue: masked -> -inf, else * alpha
// Tile 128x128, BK=8, 256 threads, 8x8 per-thread register tile.
// Requires M%128==0, N%128==0, K%8==0 (all true for this problem).
// ---------------------------------------------------------------------------
template <int BKN, int EPI>
__global__ __launch_bounds__(256, 2)
void gemm128x128(const float* __restrict__ A, const float* __restrict__ B,
                 float* __restrict__ C, int M, int N, int K,
                 long long sA, long long sB, long long sC,
                 float alpha, const unsigned char* __restrict__ mask)
{
    const int bz = blockIdx.z;
    A += (long long)bz * sA;
    B += (long long)bz * sB;
    C += (long long)bz * sC;

    __shared__ __align__(16) float As[8][132];
    __shared__ __align__(16) float Bs[8][132];

    const int tid   = threadIdx.x;
    const int tx    = tid & 15;          // 0..15 -> N direction
    const int ty    = tid >> 4;          // 0..15 -> M direction
    const int tileM = blockIdx.y * 128;
    const int tileN = blockIdx.x * 128;

    // A tile load mapping: 128 rows x 8 k, float4 along K
    const int aRow = tid >> 1;           // 0..127
    const int aCol = (tid & 1) << 2;     // 0 or 4
    const float* Ap = A + (long long)(tileM + aRow) * K + aCol;

    const float* Bp;
    int bRow = 0, bCol = 0;
    if (BKN) {                           // B[K,N]: 8 k-rows x 128 n, float4 along N
        bRow = tid >> 5;                 // 0..7
        bCol = (tid & 31) << 2;          // 0..124
        Bp = B + (long long)bRow * N + tileN + bCol;
    } else {                             // B[N,K]: same mapping as A
        Bp = B + (long long)(tileN + aRow) * K + aCol;
    }

    float acc[8][8];
#pragma unroll
    for (int i = 0; i < 8; i++)
#pragma unroll
        for (int j = 0; j < 8; j++) acc[i][j] = 0.f;

    for (int k0 = 0; k0 < K; k0 += 8) {
        float4 av = *(const float4*)(Ap + k0);
        As[aCol + 0][aRow] = av.x;
        As[aCol + 1][aRow] = av.y;
        As[aCol + 2][aRow] = av.z;
        As[aCol + 3][aRow] = av.w;
        if (BKN) {
            float4 bv = *(const float4*)(Bp + (long long)k0 * N);
            *(float4*)&Bs[bRow][bCol] = bv;
        } else {
            float4 bv = *(const float4*)(Bp + k0);
            Bs[aCol + 0][aRow] = bv.x;
            Bs[aCol + 1][aRow] = bv.y;
            Bs[aCol + 2][aRow] = bv.z;
            Bs[aCol + 3][aRow] = bv.w;
        }
        __syncthreads();
#pragma unroll
        for (int kk = 0; kk < 8; kk++) {
            float4 a0 = *(const float4*)&As[kk][ty * 8];
            float4 a1 = *(const float4*)&As[kk][ty * 8 + 4];
            float4 b0 = *(const float4*)&Bs[kk][tx * 8];
            float4 b1 = *(const float4*)&Bs[kk][tx * 8 + 4];
            float ar[8] = {a0.x, a0.y, a0.z, a0.w, a1.x, a1.y, a1.z, a1.w};
            float br[8] = {b0.x, b0.y, b0.z, b0.w, b1.x, b1.y, b1.z, b1.w};
#pragma unroll
            for (int i = 0; i < 8; i++)
#pragma unroll
                for (int j = 0; j < 8; j++)
                    acc[i][j] = fmaf(ar[i], br[j], acc[i][j]);
        }
        __syncthreads();
    }

    const float NEG_INF = __int_as_float(0xff800000);
#pragma unroll
    for (int i = 0; i < 8; i++) {
        int row = tileM + ty * 8 + i;
        long long cbase = (long long)row * N + tileN + tx * 8;
        float out[8];
        if (EPI == 1) {
            long long mbase = (long long)bz * ((long long)M * N) + cbase;
#pragma unroll
            for (int j = 0; j < 8; j++) {
                bool mk = mask_at(mask, mbase + j);
                out[j] = mk ? NEG_INF : acc[i][j] * alpha;
            }
        } else {
#pragma unroll
            for (int j = 0; j < 8; j++) out[j] = acc[i][j];
        }
        *(float4*)&C[cbase]     = make_float4(out[0], out[1], out[2], out[3]);
        *(float4*)&C[cbase + 4] = make_float4(out[4], out[5], out[6], out[7]);
    }
}

// ---------------------------------------------------------------------------
// Row softmax over LSEQ=2048 columns. One block (256 threads) per row.
// Masked entries already hold -inf -> exp() == 0.
// ---------------------------------------------------------------------------
__global__ void softmax_rows(float* __restrict__ S) {
    float* row = S + (long long)blockIdx.x * LSEQ;
    const int tid = threadIdx.x;   // 256 threads, 8 elems each

    float v[8];
    float mx = -3.4e38f;
#pragma unroll
    for (int i = 0; i < 8; i++) {
        v[i] = row[tid + (i << 8)];
        mx = fmaxf(mx, v[i]);
    }
    __shared__ float red[8];
#pragma unroll
    for (int o = 16; o > 0; o >>= 1)
        mx = fmaxf(mx, __shfl_xor_sync(0xffffffffu, mx, o));
    if ((tid & 31) == 0) red[tid >> 5] = mx;
    __syncthreads();
    mx = red[0];
#pragma unroll
    for (int w = 1; w < 8; w++) mx = fmaxf(mx, red[w]);
    __syncthreads();

    float s = 0.f;
#pragma unroll
    for (int i = 0; i < 8; i++) {
        v[i] = __expf(v[i] - mx);
        s += v[i];
    }
#pragma unroll
    for (int o = 16; o > 0; o >>= 1)
        s += __shfl_xor_sync(0xffffffffu, s, o);
    if ((tid & 31) == 0) red[tid >> 5] = s;
    __syncthreads();
    s = 0.f;
#pragma unroll
    for (int w = 0; w < 8; w++) s += red[w];

    float inv = 1.0f / s;
#pragma unroll
    for (int i = 0; i < 8; i++)
        row[tid + (i << 8)] = v[i] * inv;
}

// ---------------------------------------------------------------------------
// Launch
// Inputs: 0=q 1=k 2=v 3=softmax_mask 4=Wq 5=Wk 6=Wv 7=Wfc
// Output: concat(x [B,L,1024], ctx [B,L,512]) as float
// ---------------------------------------------------------------------------
extern "C" void kernel_launch(void* const* d_in, const int* in_sizes, int n_in,
                              void* d_out, int out_size)
{
    const float* q    = (const float*)d_in[0];
    const float* k    = (const float*)d_in[1];
    const float* v    = (const float*)d_in[2];
    const unsigned char* mask = (const unsigned char*)d_in[3];
    const float* Wq   = (const float*)d_in[4];
    const float* Wk   = (const float*)d_in[5];
    const float* Wv   = (const float*)d_in[6];
    const float* Wfc  = (const float*)d_in[7];

    float* out = (float*)d_out;
    float* xo  = out;             // (B,L,1024)
    float* ctx = out + X_ELEMS;   // (B,L,512)

    float *qp, *kp, *vp, *sc;
    cudaGetSymbolAddress((void**)&qp, g_qp);
    cudaGetSymbolAddress((void**)&kp, g_kp);
    cudaGetSymbolAddress((void**)&vp, g_vp);
    cudaGetSymbolAddress((void**)&sc, g_sc);

    detect_mask_kernel<<<1, 256>>>(mask);

    dim3 blk(256);

    // Projections: (B*L, DIN) @ W^T -> (B*L, 512). M=8192, N=512, K=1024.
    dim3 gp(DQK / 128, (NB * LSEQ) / 128, 1);
    gemm128x128<0, 0><<<gp, blk>>>(q, Wq, qp, NB * LSEQ, DQK, DIN, 0, 0, 0, 1.f, nullptr);
    gemm128x128<0, 0><<<gp, blk>>>(k, Wk, kp, NB * LSEQ, DQK, DIN, 0, 0, 0, 1.f, nullptr);
    gemm128x128<0, 0><<<gp, blk>>>(v, Wv, vp, NB * LSEQ, DV,  DIN, 0, 0, 0, 1.f, nullptr);

    // Scores: per batch qp @ kp^T / 8, mask -> -inf. M=N=2048, K=512.
    dim3 gs(LSEQ / 128, LSEQ / 128, NB);
    gemm128x128<0, 1><<<gs, blk>>>(qp, kp, sc, LSEQ, LSEQ, DQK,
                                   (long long)LSEQ * DQK, (long long)LSEQ * DQK,
                                   (long long)LSEQ * LSEQ,
                                   0.125f /* 1/sqrt(64) */, mask);

    // Softmax over key dim.
    softmax_rows<<<NB * LSEQ, 256>>>(sc);

    // ctx = attn @ vp. M=2048, N=512, K=2048 per batch. B is [K,N].
    dim3 gc(DV / 128, LSEQ / 128, NB);
    gemm128x128<1, 0><<<gc, blk>>>(sc, vp, ctx, LSEQ, DV, LSEQ,
                                   (long long)LSEQ * LSEQ, (long long)LSEQ * DV,
                                   (long long)LSEQ * DV, 1.f, nullptr);

    // x = ctx @ Wfc^T. Batches merge: M=8192, N=1024, K=512.
    dim3 gx(DIN / 128, (NB * LSEQ) / 128, 1);
    gemm128x128<0, 0><<<gx, blk>>>(ctx, Wfc, xo, NB * LSEQ, DIN, DV, 0, 0, 0, 1.f, nullptr);
}